// round 15
// baseline (speedup 1.0000x reference)
#include <cuda_runtime.h>

// ---------------------------------------------------------------------------
// MultiHeadAttention: out = softmax_causal((xWq)(xWk)^T / 8) (xWv) @ W_out
// B=4, T=2048, D=1024, H=16, DH=64. All fp32.
// Stage 1: qkv = x @ W_qkv            (8192 x 1024) @ (1024 x 3072)
// Stage 2: flash-style causal attention per (64-query tile, b*h)
// Stage 3: out = att @ W_out          (8192 x 1024) @ (1024 x 1024)
// Hot loops use packed fma.rn.f32x2 (Blackwell FFMA2) — bit-identical fp32
// math, 2 FMAs per instruction (3-reg scalar FFMA is only half-rate on
// sm_103a, so FFMA2 is required for full fp32 throughput). Attention uses
// 96KB DYNAMIC smem with K/V double buffering (2 barriers per key tile).
// ---------------------------------------------------------------------------

#define TT     2048
#define BBATCH 4
#define DMODEL 1024
#define NH     16
#define DH     64
#define MROWS  (BBATCH * TT)        // 8192
#define QKVLD  (3 * DMODEL)         // 3072

// Scratch (device globals: no runtime allocation allowed)
__device__ float g_qkv[MROWS * QKVLD];   // 96 MB
__device__ float g_att[MROWS * DMODEL];  // 32 MB

// ---- packed f32x2 helpers --------------------------------------------------
__device__ __forceinline__ unsigned long long pack2(float lo, float hi) {
    unsigned long long r;
    asm("mov.b64 %0, {%1, %2};" : "=l"(r) : "f"(lo), "f"(hi));
    return r;
}
__device__ __forceinline__ void ffma2(unsigned long long& d,
                                      unsigned long long a,
                                      unsigned long long b,
                                      unsigned long long c) {
    asm("fma.rn.f32x2 %0, %1, %2, %3;" : "=l"(d) : "l"(a), "l"(b), "l"(c));
}
__device__ __forceinline__ float2 unpack2(unsigned long long v) {
    float lo, hi;
    asm("mov.b64 {%0, %1}, %2;" : "=f"(lo), "=f"(hi) : "l"(v));
    return make_float2(lo, hi);
}

// ---------------------------------------------------------------------------
// SGEMM: C[M,N] = A[M,K] @ B[K,N], row-major, dims multiples of tile sizes.
// 128x128 block tile, BK=16, 8x8 per-thread microtile, 256 threads.
// Register-staged DOUBLE-BUFFERED smem (32KB static): 1 barrier per k-tile.
// Inner loop: 32 FFMA2 per k-step (accumulators packed along N).
// ---------------------------------------------------------------------------
__global__ __launch_bounds__(256, 2) void sgemm_kernel(
    const float* __restrict__ A, const float* __restrict__ B,
    float* __restrict__ C, int M, int N, int K)
{
    constexpr int BM = 128, BN = 128, BK = 16;
    __shared__ float As[2][BK][BM];
    __shared__ float Bs[2][BK][BN];

    const int tid = threadIdx.x;
    const int tx  = tid & 15;        // 0..15 (N dir)
    const int ty  = tid >> 4;        // 0..15 (M dir)
    const int row0 = blockIdx.y * BM;
    const int col0 = blockIdx.x * BN;

    const int aRow = tid >> 1;             // 0..127
    const int aCol = (tid & 1) * 8;        // 0 or 8
    const int bRow = tid >> 5;             // 0..7
    const int bCol = (tid & 31) * 4;       // 0..124

    const float* Aptr = A + (row0 + aRow) * K + aCol;
    const float* Bptr = B + bRow * N + col0 + bCol;

    const int ntiles = K / BK;

    // Prologue: tile 0 -> buffer 0
    {
        float4 a0 = *(const float4*)(Aptr);
        float4 a1 = *(const float4*)(Aptr + 4);
        float4 b0 = *(const float4*)(Bptr);
        float4 b1 = *(const float4*)(Bptr + 8 * N);
        As[0][aCol + 0][aRow] = a0.x;
        As[0][aCol + 1][aRow] = a0.y;
        As[0][aCol + 2][aRow] = a0.z;
        As[0][aCol + 3][aRow] = a0.w;
        As[0][aCol + 4][aRow] = a1.x;
        As[0][aCol + 5][aRow] = a1.y;
        As[0][aCol + 6][aRow] = a1.z;
        As[0][aCol + 7][aRow] = a1.w;
        *(float4*)&Bs[0][bRow][bCol]     = b0;
        *(float4*)&Bs[0][bRow + 8][bCol] = b1;
    }
    __syncthreads();

    // Packed accumulators: acc2[i][jp] = (C[i][2jp], C[i][2jp+1])
    unsigned long long acc2[8][4];
#pragma unroll
    for (int i = 0; i < 8; i++)
#pragma unroll
        for (int j = 0; j < 4; j++) acc2[i][j] = 0ull;

#pragma unroll 1
    for (int t = 0; t < ntiles; t++) {
        const int cur = t & 1;
        float4 a0, a1, b0, b1;
        const bool more = (t + 1 < ntiles);
        if (more) {
            const int k0 = (t + 1) * BK;
            a0 = *(const float4*)(Aptr + k0);          // 4 independent LDG.128
            a1 = *(const float4*)(Aptr + k0 + 4);      // in flight during compute
            b0 = *(const float4*)(Bptr + k0 * N);
            b1 = *(const float4*)(Bptr + (k0 + 8) * N);
        }

#pragma unroll
        for (int k = 0; k < BK; k++) {
            float ar[8];
            *(float4*)&ar[0] = *(const float4*)&As[cur][k][ty * 8];
            *(float4*)&ar[4] = *(const float4*)&As[cur][k][ty * 8 + 4];
            ulonglong2 bp0 = *(const ulonglong2*)&Bs[cur][k][tx * 8];
            ulonglong2 bp1 = *(const ulonglong2*)&Bs[cur][k][tx * 8 + 4];
#pragma unroll
            for (int i = 0; i < 8; i++) {
                unsigned long long ad = pack2(ar[i], ar[i]);
                ffma2(acc2[i][0], ad, bp0.x, acc2[i][0]);
                ffma2(acc2[i][1], ad, bp0.y, acc2[i][1]);
                ffma2(acc2[i][2], ad, bp1.x, acc2[i][2]);
                ffma2(acc2[i][3], ad, bp1.y, acc2[i][3]);
            }
        }

        if (more) {
            const int nxt = cur ^ 1;
            As[nxt][aCol + 0][aRow] = a0.x;
            As[nxt][aCol + 1][aRow] = a0.y;
            As[nxt][aCol + 2][aRow] = a0.z;
            As[nxt][aCol + 3][aRow] = a0.w;
            As[nxt][aCol + 4][aRow] = a1.x;
            As[nxt][aCol + 5][aRow] = a1.y;
            As[nxt][aCol + 6][aRow] = a1.z;
            As[nxt][aCol + 7][aRow] = a1.w;
            *(float4*)&Bs[nxt][bRow][bCol]     = b0;
            *(float4*)&Bs[nxt][bRow + 8][bCol] = b1;
            __syncthreads();
        }
    }

    // Epilogue: packed u64 bit-layout == (float lo, float hi) in memory order
#pragma unroll
    for (int i = 0; i < 8; i++) {
        float* Crow = C + (row0 + ty * 8 + i) * N + col0 + tx * 8;
        *(ulonglong2*)Crow       = make_ulonglong2(acc2[i][0], acc2[i][1]);
        *(ulonglong2*)(Crow + 4) = make_ulonglong2(acc2[i][2], acc2[i][3]);
    }
}

// ---------------------------------------------------------------------------
// Causal flash attention with K/V DOUBLE BUFFERING (dynamic smem, 96KB).
// grid: (T/64, B*H); block: 256 threads (16x16), 4x4 microtile.
// Dynamic smem layout (floats): Qt[4096] | Kt[2][4096] | Vs[2][4096] | Ps[4096]
//   Qt[d*64+q] transposed, pre-scaled by 1/8; Kt[d*64+k]; Vs[k*64+d]; Ps[q*64+k].
// Per key-tile iteration: exactly 2 __syncthreads().
//   bar(top): prev PV done (Ps/Vs WAR), buf 'cur' stores visible.
//   body:     issue LDG t+1 -> S-GEMM(cur) -> commit->cur^1 -> softmax->Ps
//   bar(mid): Ps visible; then PV(Ps, Vs[cur]).
// Prologue issues ALL 12 LDG.128 (Q + K/V tile 0) before any smem store.
// ---------------------------------------------------------------------------
#define ATTN_SMEM_BYTES (6 * 4096 * 4)   // 96 KB

__global__ __launch_bounds__(256, 2) void attn_kernel(
    const float* __restrict__ qkv, float* __restrict__ outp)
{
    extern __shared__ float sm[];
    float* Qt  = sm;                 // 4096
    float* KtB = sm + 4096;          // 2 x 4096
    float* VsB = sm + 3 * 4096;      // 2 x 4096
    float* Ps  = sm + 5 * 4096;      // 4096

    const int tid = threadIdx.x;
    const int tx  = tid & 15;       // key/dim direction
    const int ty  = tid >> 4;       // query direction
    const int qi  = (int)gridDim.x - 1 - (int)blockIdx.x;  // big tiles first
    const int bh  = blockIdx.y;
    const int b   = bh >> 4;
    const int h   = bh & 15;
    const int hcol  = h * DH;
    const int qbase = b * TT + qi * 64;   // first query row (in B*T space)

    const int tok0 = tid >> 4;          // 0..15, +16 per chunk
    const int d4   = (tid & 15) * 4;    // 0..60

    const float scale = 0.125f;   // 1/sqrt(64); exact power-of-two scaling

    // Prologue: issue ALL independent global loads first (MLP=12), then commit.
    float4 qreg[4], kreg[4], vreg[4];
    {
        const int kbase = b * TT;
#pragma unroll
        for (int c = 0; c < 4; c++) {
            int tok = tok0 + c * 16;
            qreg[c] = *(const float4*)&qkv[(qbase + tok) * QKVLD + hcol + d4];
            const float* base = &qkv[(kbase + tok) * QKVLD + hcol + d4];
            kreg[c] = *(const float4*)(base + DMODEL);
            vreg[c] = *(const float4*)(base + 2 * DMODEL);
        }
        // Commit Q transposed + pre-scaled, K transposed, V natural.
#pragma unroll
        for (int c = 0; c < 4; c++) {
            int tok = tok0 + c * 16;
            Qt[(d4 + 0) * 64 + tok] = qreg[c].x * scale;
            Qt[(d4 + 1) * 64 + tok] = qreg[c].y * scale;
            Qt[(d4 + 2) * 64 + tok] = qreg[c].z * scale;
            Qt[(d4 + 3) * 64 + tok] = qreg[c].w * scale;
            KtB[(d4 + 0) * 64 + tok] = kreg[c].x;
            KtB[(d4 + 1) * 64 + tok] = kreg[c].y;
            KtB[(d4 + 2) * 64 + tok] = kreg[c].z;
            KtB[(d4 + 3) * 64 + tok] = kreg[c].w;
            *(float4*)&VsB[tok * 64 + d4] = vreg[c];
        }
    }

    float m_i[4], l_i[4];
    unsigned long long o2[4][2];   // packed O accum
#pragma unroll
    for (int i = 0; i < 4; i++) {
        m_i[i] = -1e30f; l_i[i] = 0.f;
        o2[i][0] = 0ull; o2[i][1] = 0ull;
    }

#pragma unroll 1
    for (int kt = 0; kt <= qi; kt++) {
        const int cur = kt & 1;
        const float* Kc = KtB + cur * 4096;
        const float* Vc = VsB + cur * 4096;
        float* Kn = KtB + (cur ^ 1) * 4096;
        float* Vn = VsB + (cur ^ 1) * 4096;

        __syncthreads();   // bar(top): prev PV done; buf 'cur' visible (and Qt at kt=0)

        // Issue next tile's global loads (land during S-GEMM)
        if (kt < qi) {
            const int kbase = b * TT + (kt + 1) * 64;
#pragma unroll
            for (int c = 0; c < 4; c++) {
                const float* base = &qkv[(kbase + tok0 + c * 16) * QKVLD + hcol + d4];
                kreg[c] = *(const float4*)(base + DMODEL);
                vreg[c] = *(const float4*)(base + 2 * DMODEL);
            }
        }

        // S = (Q/8) K^T, packed along key axis: s2[i][jp]
        unsigned long long s2[4][2];
#pragma unroll
        for (int i = 0; i < 4; i++) { s2[i][0] = 0ull; s2[i][1] = 0ull; }

#pragma unroll 16
        for (int d = 0; d < 64; d++) {
            float4 a = *(const float4*)&Qt[d * 64 + ty * 4];
            ulonglong2 bp = *(const ulonglong2*)&Kc[d * 64 + tx * 4];  // 16B aligned
            float ar[4] = {a.x, a.y, a.z, a.w};
#pragma unroll
            for (int i = 0; i < 4; i++) {
                unsigned long long ad = pack2(ar[i], ar[i]);
                ffma2(s2[i][0], ad, bp.x, s2[i][0]);
                ffma2(s2[i][1], ad, bp.y, s2[i][1]);
            }
        }

        // Commit next K/V tile into the OTHER buffer EARLY (before softmax):
        // STS drains while the shfl chain runs, shrinking bar(mid)'s drain
        // term. WAR vs prev iter's readers covered by bar(top) of this iter;
        // visibility to next iter's readers by bar(top) of next iter.
        if (kt < qi) {
#pragma unroll
            for (int c = 0; c < 4; c++) {
                int tok = tok0 + c * 16;
                Kn[(d4 + 0) * 64 + tok] = kreg[c].x;
                Kn[(d4 + 1) * 64 + tok] = kreg[c].y;
                Kn[(d4 + 2) * 64 + tok] = kreg[c].z;
                Kn[(d4 + 3) * 64 + tok] = kreg[c].w;
                *(float4*)&Vn[tok * 64 + d4] = vreg[c];
            }
        }

        // Unpack S to scalars for mask + softmax
        float s[4][4];
#pragma unroll
        for (int i = 0; i < 4; i++) {
            float2 lo = unpack2(s2[i][0]);
            float2 hi = unpack2(s2[i][1]);
            s[i][0] = lo.x; s[i][1] = lo.y; s[i][2] = hi.x; s[i][3] = hi.y;
        }

        // Causal mask on diagonal tile
        if (kt == qi) {
#pragma unroll
            for (int i = 0; i < 4; i++)
#pragma unroll
                for (int j = 0; j < 4; j++)
                    if (tx * 4 + j > ty * 4 + i) s[i][j] = -1e30f;
        }

        // Online softmax per query row (16 lanes share a row, within a warp half)
#pragma unroll
        for (int i = 0; i < 4; i++) {
            float mt = fmaxf(fmaxf(s[i][0], s[i][1]), fmaxf(s[i][2], s[i][3]));
#pragma unroll
            for (int off = 1; off < 16; off <<= 1)
                mt = fmaxf(mt, __shfl_xor_sync(0xffffffffu, mt, off));
            float mnew = fmaxf(m_i[i], mt);
            float corr = __expf(m_i[i] - mnew);
            float p0 = __expf(s[i][0] - mnew);
            float p1 = __expf(s[i][1] - mnew);
            float p2 = __expf(s[i][2] - mnew);
            float p3 = __expf(s[i][3] - mnew);
            *(float4*)&Ps[(ty * 4 + i) * 64 + tx * 4] = make_float4(p0, p1, p2, p3);
            float rs = p0 + p1 + p2 + p3;
#pragma unroll
            for (int off = 1; off < 16; off <<= 1)
                rs += __shfl_xor_sync(0xffffffffu, rs, off);
            l_i[i] = l_i[i] * corr + rs;
            m_i[i] = mnew;
            unsigned long long cd = pack2(corr, corr);
            unsigned long long zero = 0ull;
            ffma2(o2[i][0], o2[i][0], cd, zero);
            ffma2(o2[i][1], o2[i][1], cd, zero);
        }

        __syncthreads();   // bar(mid): Ps visible before PV

        // O += P @ V, packed along dim axis
#pragma unroll 4
        for (int k4 = 0; k4 < 64; k4 += 4) {
            ulonglong2 vp0 = *(const ulonglong2*)&Vc[(k4 + 0) * 64 + tx * 4];
            ulonglong2 vp1 = *(const ulonglong2*)&Vc[(k4 + 1) * 64 + tx * 4];
            ulonglong2 vp2 = *(const ulonglong2*)&Vc[(k4 + 2) * 64 + tx * 4];
            ulonglong2 vp3 = *(const ulonglong2*)&Vc[(k4 + 3) * 64 + tx * 4];
#pragma unroll
            for (int i = 0; i < 4; i++) {
                float4 pr = *(const float4*)&Ps[(ty * 4 + i) * 64 + k4];
                unsigned long long pd;
                pd = pack2(pr.x, pr.x);
                ffma2(o2[i][0], pd, vp0.x, o2[i][0]);
                ffma2(o2[i][1], pd, vp0.y, o2[i][1]);
                pd = pack2(pr.y, pr.y);
                ffma2(o2[i][0], pd, vp1.x, o2[i][0]);
                ffma2(o2[i][1], pd, vp1.y, o2[i][1]);
                pd = pack2(pr.z, pr.z);
                ffma2(o2[i][0], pd, vp2.x, o2[i][0]);
                ffma2(o2[i][1], pd, vp2.y, o2[i][1]);
                pd = pack2(pr.w, pr.w);
                ffma2(o2[i][0], pd, vp3.x, o2[i][0]);
                ffma2(o2[i][1], pd, vp3.y, o2[i][1]);
            }
        }
    }

    // Finalize and write: out[(b*T + q)][h*64 + d]
#pragma unroll
    for (int i = 0; i < 4; i++) {
        float inv = 1.f / l_i[i];
        float2 c0 = unpack2(o2[i][0]);
        float2 c1 = unpack2(o2[i][1]);
        float* dst = &outp[(qbase + ty * 4 + i) * DMODEL + hcol + tx * 4];
        *(float4*)dst = make_float4(c0.x * inv, c0.y * inv,
                                    c1.x * inv, c1.y * inv);
    }
}

// ---------------------------------------------------------------------------
extern "C" void kernel_launch(void* const* d_in, const int* in_sizes, int n_in,
                              void* d_out, int out_size)
{
    const float* x    = (const float*)d_in[0];
    const float* Wqkv = (const float*)d_in[1];
    const float* Wout = (const float*)d_in[2];
    // d_in[3] = mask (int32 tril) — causality handled analytically.
    float* out = (float*)d_out;

    float *qkv_s, *att_s;
    cudaGetSymbolAddress((void**)&qkv_s, g_qkv);
    cudaGetSymbolAddress((void**)&att_s, g_att);

    // Opt-in to >48KB dynamic smem for the attention kernel (host-side
    // attribute set; not a stream op, legal under graph capture).
    cudaFuncSetAttribute(attn_kernel,
                         cudaFuncAttributeMaxDynamicSharedMemorySize,
                         ATTN_SMEM_BYTES);

    // Stage 1: qkv = x @ W_qkv
    dim3 g1(QKVLD / 128, MROWS / 128);
    sgemm_kernel<<<g1, 256>>>(x, Wqkv, qkv_s, MROWS, QKVLD, DMODEL);

    // Stage 2: causal attention
    dim3 g2(TT / 64, BBATCH * NH);
    attn_kernel<<<g2, 256, ATTN_SMEM_BYTES>>>(qkv_s, att_s);

    // Stage 3: out = att @ W_out
    dim3 g3(DMODEL / 128, MROWS / 128);
    sgemm_kernel<<<g3, 256>>>(att_s, Wout, out, MROWS, DMODEL, DMODEL);
}

// round 17
// speedup vs baseline: 1.2441x; 1.2441x over previous
#include <cuda_runtime.h>
#include <cuda_bf16.h>

// ---------------------------------------------------------------------------
// MultiHeadAttention: out = softmax_causal((xWq)(xWk)^T / 8) (xWv) @ W_out
// B=4, T=2048, D=1024, H=16, DH=64. fp32 in/out.
// Stage 1/3 GEMMs: TENSOR CORES via mma.sync.m16n8k16.bf16 with bf16x3
//   (split x = hi + lo, acc = hi*hi + hi*lo + lo*hi in fp32) — rel err ~4e-6.
// Stage 2 attention: FFMA2 flash kernel (validated at rel_err 6.5e-7).
// ---------------------------------------------------------------------------

#define TT     2048
#define BBATCH 4
#define DMODEL 1024
#define NH     16
#define DH     64
#define MROWS  (BBATCH * TT)        // 8192
#define QKVLD  (3 * DMODEL)         // 3072

__device__ float g_qkv[MROWS * QKVLD];   // 96 MB scratch
__device__ float g_att[MROWS * DMODEL];  // 32 MB scratch

// ---- packed f32x2 helpers (attention) --------------------------------------
__device__ __forceinline__ unsigned long long pack2(float lo, float hi) {
    unsigned long long r;
    asm("mov.b64 %0, {%1, %2};" : "=l"(r) : "f"(lo), "f"(hi));
    return r;
}
__device__ __forceinline__ void ffma2(unsigned long long& d,
                                      unsigned long long a,
                                      unsigned long long b,
                                      unsigned long long c) {
    asm("fma.rn.f32x2 %0, %1, %2, %3;" : "=l"(d) : "l"(a), "l"(b), "l"(c));
}
__device__ __forceinline__ float2 unpack2(unsigned long long v) {
    float lo, hi;
    asm("mov.b64 {%0, %1}, %2;" : "=f"(lo), "=f"(hi) : "l"(v));
    return make_float2(lo, hi);
}

// ---- bf16 split + mma helpers (GEMM) ---------------------------------------
__device__ __forceinline__ void split_bf16(float x, __nv_bfloat16& h, __nv_bfloat16& l) {
    h = __float2bfloat16(x);
    l = __float2bfloat16(x - __bfloat162float(h));
}
// D += A(16x16 bf16, row) * B(16x8 bf16, col); accumulate in fp32.
__device__ __forceinline__ void mma16816(float& d0, float& d1, float& d2, float& d3,
                                         unsigned a0, unsigned a1, unsigned a2, unsigned a3,
                                         unsigned b0, unsigned b1) {
    asm volatile(
        "mma.sync.aligned.m16n8k16.row.col.f32.bf16.bf16.f32 "
        "{%0,%1,%2,%3}, {%4,%5,%6,%7}, {%8,%9}, {%0,%1,%2,%3};"
        : "+f"(d0), "+f"(d1), "+f"(d2), "+f"(d3)
        : "r"(a0), "r"(a1), "r"(a2), "r"(a3), "r"(b0), "r"(b1));
}

// ---------------------------------------------------------------------------
// Tensor-core SGEMM: C[M,N] = A[M,K] @ B[K,N], fp32 via bf16x3.
// 128x128 CTA tile, BK=16, 256 threads = 8 warps in 2(M)x4(N), warp tile 64x32.
// smem: A hi/lo as [m][k] bf16, B hi/lo transposed as [n][k] bf16, rows padded
// to 18 bf16; arrays 16B-aligned so all 4B fragment loads are aligned.
// Double-buffered, 1 barrier/tile.
// ---------------------------------------------------------------------------
#define AP 18   // padded row length (bf16 elems); 36B row stride (4B-divisible)

__global__ __launch_bounds__(256, 2) void sgemm_mma_kernel(
    const float* __restrict__ A, const float* __restrict__ B,
    float* __restrict__ C, int M, int N, int K)
{
    constexpr int BM = 128, BN = 128, BK = 16;
    __shared__ __align__(16) __nv_bfloat16 Ah[2][BM][AP], Al[2][BM][AP];
    __shared__ __align__(16) __nv_bfloat16 Bh[2][BN][AP], Bl[2][BN][AP];  // B^T: [n][k]

    const int tid  = threadIdx.x;
    const int lane = tid & 31;
    const int warp = tid >> 5;
    const int wm   = (warp >> 2) * 64;   // warp tile M origin (0 or 64)
    const int wn   = (warp & 3) * 32;    // warp tile N origin (0,32,64,96)
    const int r    = lane >> 2;          // 0..7
    const int cc   = (lane & 3) * 2;     // 0,2,4,6

    const int row0 = blockIdx.y * BM;
    const int col0 = blockIdx.x * BN;

    // Global-load mapping: A: thread -> (m = tid/2, kc = (tid&1)*8), 8 floats.
    //                      B: thread -> (kr = tid/32, n4 = (tid&31)*4), rows kr & kr+8.
    const int am = tid >> 1;
    const int ak = (tid & 1) * 8;
    const int bk = tid >> 5;             // 0..7
    const int bn = (tid & 31) * 4;

    const float* Aptr = A + (row0 + am) * K + ak;
    const float* Bptr = B + bk * N + col0 + bn;

    const int ntiles = K / BK;

    // Convert+store a fetched tile into smem buffer `buf`.
    auto commit = [&](int buf, const float4& a0, const float4& a1,
                      const float4& b0, const float4& b1) {
        const float av[8] = {a0.x, a0.y, a0.z, a0.w, a1.x, a1.y, a1.z, a1.w};
#pragma unroll
        for (int j = 0; j < 8; j++)
            split_bf16(av[j], Ah[buf][am][ak + j], Al[buf][am][ak + j]);
        const float bv0[4] = {b0.x, b0.y, b0.z, b0.w};
        const float bv1[4] = {b1.x, b1.y, b1.z, b1.w};
#pragma unroll
        for (int j = 0; j < 4; j++) {
            split_bf16(bv0[j], Bh[buf][bn + j][bk],     Bl[buf][bn + j][bk]);
            split_bf16(bv1[j], Bh[buf][bn + j][bk + 8], Bl[buf][bn + j][bk + 8]);
        }
    };

    // Prologue: tile 0 -> buffer 0
    {
        float4 a0 = *(const float4*)(Aptr);
        float4 a1 = *(const float4*)(Aptr + 4);
        float4 b0 = *(const float4*)(Bptr);
        float4 b1 = *(const float4*)(Bptr + 8 * N);
        commit(0, a0, a1, b0, b1);
    }
    __syncthreads();

    float acc[4][4][4];
#pragma unroll
    for (int mt = 0; mt < 4; mt++)
#pragma unroll
        for (int nt = 0; nt < 4; nt++)
#pragma unroll
            for (int q = 0; q < 4; q++) acc[mt][nt][q] = 0.f;

#pragma unroll 1
    for (int t = 0; t < ntiles; t++) {
        const int cur = t & 1;
        float4 a0, a1, b0, b1;
        const bool more = (t + 1 < ntiles);
        if (more) {
            const int k0 = (t + 1) * BK;
            a0 = *(const float4*)(Aptr + k0);
            a1 = *(const float4*)(Aptr + k0 + 4);
            b0 = *(const float4*)(Bptr + k0 * N);
            b1 = *(const float4*)(Bptr + (k0 + 8) * N);
        }

        // Load B fragments (4 n-tiles x {hi,lo} x 2 regs)
        unsigned bh[4][2], bl[4][2];
#pragma unroll
        for (int nt = 0; nt < 4; nt++) {
            const int n0 = wn + nt * 8 + r;
            bh[nt][0] = *(const unsigned*)&Bh[cur][n0][cc];
            bh[nt][1] = *(const unsigned*)&Bh[cur][n0][cc + 8];
            bl[nt][0] = *(const unsigned*)&Bl[cur][n0][cc];
            bl[nt][1] = *(const unsigned*)&Bl[cur][n0][cc + 8];
        }

#pragma unroll
        for (int mt = 0; mt < 4; mt++) {
            const int m0 = wm + mt * 16 + r;
            unsigned ah0 = *(const unsigned*)&Ah[cur][m0][cc];
            unsigned ah1 = *(const unsigned*)&Ah[cur][m0 + 8][cc];
            unsigned ah2 = *(const unsigned*)&Ah[cur][m0][cc + 8];
            unsigned ah3 = *(const unsigned*)&Ah[cur][m0 + 8][cc + 8];
            unsigned al0 = *(const unsigned*)&Al[cur][m0][cc];
            unsigned al1 = *(const unsigned*)&Al[cur][m0 + 8][cc];
            unsigned al2 = *(const unsigned*)&Al[cur][m0][cc + 8];
            unsigned al3 = *(const unsigned*)&Al[cur][m0 + 8][cc + 8];
#pragma unroll
            for (int nt = 0; nt < 4; nt++) {
                float* d = acc[mt][nt];
                mma16816(d[0], d[1], d[2], d[3], ah0, ah1, ah2, ah3, bh[nt][0], bh[nt][1]);
                mma16816(d[0], d[1], d[2], d[3], ah0, ah1, ah2, ah3, bl[nt][0], bl[nt][1]);
                mma16816(d[0], d[1], d[2], d[3], al0, al1, al2, al3, bh[nt][0], bh[nt][1]);
            }
        }

        if (more) {
            commit(cur ^ 1, a0, a1, b0, b1);
            __syncthreads();
        }
    }

    // Epilogue: c0,c1 = C[row][col..col+1]; c2,c3 = C[row+8][col..col+1]
#pragma unroll
    for (int mt = 0; mt < 4; mt++) {
#pragma unroll
        for (int nt = 0; nt < 4; nt++) {
            const int row = row0 + wm + mt * 16 + r;
            const int col = col0 + wn + nt * 8 + cc;
            *(float2*)&C[row * N + col]       = make_float2(acc[mt][nt][0], acc[mt][nt][1]);
            *(float2*)&C[(row + 8) * N + col] = make_float2(acc[mt][nt][2], acc[mt][nt][3]);
        }
    }
}

// ---------------------------------------------------------------------------
// Causal flash attention with K/V DOUBLE BUFFERING (dynamic smem, 96KB).
// (Unchanged from the validated 2648us baseline.)
// ---------------------------------------------------------------------------
#define ATTN_SMEM_BYTES (6 * 4096 * 4)   // 96 KB

__global__ __launch_bounds__(256, 2) void attn_kernel(
    const float* __restrict__ qkv, float* __restrict__ outp)
{
    extern __shared__ float sm[];
    float* Qt  = sm;                 // 4096
    float* KtB = sm + 4096;          // 2 x 4096
    float* VsB = sm + 3 * 4096;      // 2 x 4096
    float* Ps  = sm + 5 * 4096;      // 4096

    const int tid = threadIdx.x;
    const int tx  = tid & 15;
    const int ty  = tid >> 4;
    const int qi  = (int)gridDim.x - 1 - (int)blockIdx.x;
    const int bh  = blockIdx.y;
    const int b   = bh >> 4;
    const int h   = bh & 15;
    const int hcol  = h * DH;
    const int qbase = b * TT + qi * 64;

    const int tok0 = tid >> 4;
    const int d4   = (tid & 15) * 4;

    const float scale = 0.125f;

    float4 qreg[4], kreg[4], vreg[4];
    {
        const int kbase = b * TT;
#pragma unroll
        for (int c = 0; c < 4; c++) {
            int tok = tok0 + c * 16;
            qreg[c] = *(const float4*)&qkv[(qbase + tok) * QKVLD + hcol + d4];
            const float* base = &qkv[(kbase + tok) * QKVLD + hcol + d4];
            kreg[c] = *(const float4*)(base + DMODEL);
            vreg[c] = *(const float4*)(base + 2 * DMODEL);
        }
#pragma unroll
        for (int c = 0; c < 4; c++) {
            int tok = tok0 + c * 16;
            Qt[(d4 + 0) * 64 + tok] = qreg[c].x * scale;
            Qt[(d4 + 1) * 64 + tok] = qreg[c].y * scale;
            Qt[(d4 + 2) * 64 + tok] = qreg[c].z * scale;
            Qt[(d4 + 3) * 64 + tok] = qreg[c].w * scale;
            KtB[(d4 + 0) * 64 + tok] = kreg[c].x;
            KtB[(d4 + 1) * 64 + tok] = kreg[c].y;
            KtB[(d4 + 2) * 64 + tok] = kreg[c].z;
            KtB[(d4 + 3) * 64 + tok] = kreg[c].w;
            *(float4*)&VsB[tok * 64 + d4] = vreg[c];
        }
    }

    float m_i[4], l_i[4];
    unsigned long long o2[4][2];
#pragma unroll
    for (int i = 0; i < 4; i++) {
        m_i[i] = -1e30f; l_i[i] = 0.f;
        o2[i][0] = 0ull; o2[i][1] = 0ull;
    }

#pragma unroll 1
    for (int kt = 0; kt <= qi; kt++) {
        const int cur = kt & 1;
        const float* Kc = KtB + cur * 4096;
        const float* Vc = VsB + cur * 4096;
        float* Kn = KtB + (cur ^ 1) * 4096;
        float* Vn = VsB + (cur ^ 1) * 4096;

        __syncthreads();

        if (kt < qi) {
            const int kbase = b * TT + (kt + 1) * 64;
#pragma unroll
            for (int c = 0; c < 4; c++) {
                const float* base = &qkv[(kbase + tok0 + c * 16) * QKVLD + hcol + d4];
                kreg[c] = *(const float4*)(base + DMODEL);
                vreg[c] = *(const float4*)(base + 2 * DMODEL);
            }
        }

        unsigned long long s2[4][2];
#pragma unroll
        for (int i = 0; i < 4; i++) { s2[i][0] = 0ull; s2[i][1] = 0ull; }

#pragma unroll 16
        for (int d = 0; d < 64; d++) {
            float4 a = *(const float4*)&Qt[d * 64 + ty * 4];
            ulonglong2 bp = *(const ulonglong2*)&Kc[d * 64 + tx * 4];
            float ar[4] = {a.x, a.y, a.z, a.w};
#pragma unroll
            for (int i = 0; i < 4; i++) {
                unsigned long long ad = pack2(ar[i], ar[i]);
                ffma2(s2[i][0], ad, bp.x, s2[i][0]);
                ffma2(s2[i][1], ad, bp.y, s2[i][1]);
            }
        }

        if (kt < qi) {
#pragma unroll
            for (int c = 0; c < 4; c++) {
                int tok = tok0 + c * 16;
                Kn[(d4 + 0) * 64 + tok] = kreg[c].x;
                Kn[(d4 + 1) * 64 + tok] = kreg[c].y;
                Kn[(d4 + 2) * 64 + tok] = kreg[c].z;
                Kn[(d4 + 3) * 64 + tok] = kreg[c].w;
                *(float4*)&Vn[tok * 64 + d4] = vreg[c];
            }
        }

        float s[4][4];
#pragma unroll
        for (int i = 0; i < 4; i++) {
            float2 lo = unpack2(s2[i][0]);
            float2 hi = unpack2(s2[i][1]);
            s[i][0] = lo.x; s[i][1] = lo.y; s[i][2] = hi.x; s[i][3] = hi.y;
        }

        if (kt == qi) {
#pragma unroll
            for (int i = 0; i < 4; i++)
#pragma unroll
                for (int j = 0; j < 4; j++)
                    if (tx * 4 + j > ty * 4 + i) s[i][j] = -1e30f;
        }

#pragma unroll
        for (int i = 0; i < 4; i++) {
            float mt = fmaxf(fmaxf(s[i][0], s[i][1]), fmaxf(s[i][2], s[i][3]));
#pragma unroll
            for (int off = 1; off < 16; off <<= 1)
                mt = fmaxf(mt, __shfl_xor_sync(0xffffffffu, mt, off));
            float mnew = fmaxf(m_i[i], mt);
            float corr = __expf(m_i[i] - mnew);
            float p0 = __expf(s[i][0] - mnew);
            float p1 = __expf(s[i][1] - mnew);
            float p2 = __expf(s[i][2] - mnew);
            float p3 = __expf(s[i][3] - mnew);
            *(float4*)&Ps[(ty * 4 + i) * 64 + tx * 4] = make_float4(p0, p1, p2, p3);
            float rs = p0 + p1 + p2 + p3;
#pragma unroll
            for (int off = 1; off < 16; off <<= 1)
                rs += __shfl_xor_sync(0xffffffffu, rs, off);
            l_i[i] = l_i[i] * corr + rs;
            m_i[i] = mnew;
            unsigned long long cd = pack2(corr, corr);
            unsigned long long zero = 0ull;
            ffma2(o2[i][0], o2[i][0], cd, zero);
            ffma2(o2[i][1], o2[i][1], cd, zero);
        }

        __syncthreads();

#pragma unroll 4
        for (int k4 = 0; k4 < 64; k4 += 4) {
            ulonglong2 vp0 = *(const ulonglong2*)&Vc[(k4 + 0) * 64 + tx * 4];
            ulonglong2 vp1 = *(const ulonglong2*)&Vc[(k4 + 1) * 64 + tx * 4];
            ulonglong2 vp2 = *(const ulonglong2*)&Vc[(k4 + 2) * 64 + tx * 4];
            ulonglong2 vp3 = *(const ulonglong2*)&Vc[(k4 + 3) * 64 + tx * 4];
#pragma unroll
            for (int i = 0; i < 4; i++) {
                float4 pr = *(const float4*)&Ps[(ty * 4 + i) * 64 + k4];
                unsigned long long pd;
                pd = pack2(pr.x, pr.x);
                ffma2(o2[i][0], pd, vp0.x, o2[i][0]);
                ffma2(o2[i][1], pd, vp0.y, o2[i][1]);
                pd = pack2(pr.y, pr.y);
                ffma2(o2[i][0], pd, vp1.x, o2[i][0]);
                ffma2(o2[i][1], pd, vp1.y, o2[i][1]);
                pd = pack2(pr.z, pr.z);
                ffma2(o2[i][0], pd, vp2.x, o2[i][0]);
                ffma2(o2[i][1], pd, vp2.y, o2[i][1]);
                pd = pack2(pr.w, pr.w);
                ffma2(o2[i][0], pd, vp3.x, o2[i][0]);
                ffma2(o2[i][1], pd, vp3.y, o2[i][1]);
            }
        }
    }

#pragma unroll
    for (int i = 0; i < 4; i++) {
        float inv = 1.f / l_i[i];
        float2 c0 = unpack2(o2[i][0]);
        float2 c1 = unpack2(o2[i][1]);
        float* dst = &outp[(qbase + ty * 4 + i) * DMODEL + hcol + tx * 4];
        *(float4*)dst = make_float4(c0.x * inv, c0.y * inv,
                                    c1.x * inv, c1.y * inv);
    }
}

// ---------------------------------------------------------------------------
extern "C" void kernel_launch(void* const* d_in, const int* in_sizes, int n_in,
                              void* d_out, int out_size)
{
    const float* x    = (const float*)d_in[0];
    const float* Wqkv = (const float*)d_in[1];
    const float* Wout = (const float*)d_in[2];
    // d_in[3] = mask (int32 tril) — causality handled analytically.
    float* out = (float*)d_out;

    float *qkv_s, *att_s;
    cudaGetSymbolAddress((void**)&qkv_s, g_qkv);
    cudaGetSymbolAddress((void**)&att_s, g_att);

    cudaFuncSetAttribute(attn_kernel,
                         cudaFuncAttributeMaxDynamicSharedMemorySize,
                         ATTN_SMEM_BYTES);

    // Stage 1: qkv = x @ W_qkv (tensor cores, bf16x3)
    dim3 g1(QKVLD / 128, MROWS / 128);
    sgemm_mma_kernel<<<g1, 256>>>(x, Wqkv, qkv_s, MROWS, QKVLD, DMODEL);

    // Stage 2: causal attention
    dim3 g2(TT / 64, BBATCH * NH);
    attn_kernel<<<g2, 256, ATTN_SMEM_BYTES>>>(qkv_s, att_s);

    // Stage 3: out = att @ W_out (tensor cores, bf16x3)
    dim3 g3(DMODEL / 128, MROWS / 128);
    sgemm_mma_kernel<<<g3, 256>>>(att_s, Wout, out, MROWS, DMODEL, DMODEL);
}